// round 5
// baseline (speedup 1.0000x reference)
#include <cuda_runtime.h>
#include <cuda_bf16.h>
#include <math.h>

#define CELLN 14
#define NCLS  80
#define BPC   3
#define FEAT  95            // 80 + 3 + 12
#define CELLS2 196          // 14*14
#define PRED_PER_B 18620    // 196*95
#define CSF   32.0f
#define IMGF  448.0f
#define EPSF  1e-9f
#define INV_PI2_4 0.40528473456935109f   // 4/pi^2
#define MAXB  4096
#define MAXOBJ 32

__device__ float g_batch_loss[MAXB];
__device__ int   g_count = 0;

// Per-cell phase-1 body: stats + smem tail store + fold-in of p_k for every
// object whose mask covers this cell (coverage bitmask, shfl extraction).
__device__ __forceinline__ void process_cell(
    int cell, float a, float bv, float c, int lane, int wid,
    float& conf2, float* __restrict__ spart, float* __restrict__ scell,
    const unsigned* __restrict__ scover, const int* __restrict__ sk,
    float* __restrict__ sobj_part)
{
    float part = a * a + bv * bv;          // features [0,64)
    const float c2 = c * c;
    if (lane < 16) part += c2;             // 64..79 (class)
    else if (lane < 19) conf2 += c2;       // 80..82 (confidence)
    if (lane >= 16 && lane < 31)
        scell[cell * 16 + (lane - 16)] = c;   // 80..94

    part += __shfl_xor_sync(0xFFFFFFFFu, part, 16);
    if (lane < 16) spart[cell * 17 + lane] = part;

    unsigned cov = scover[cell];
    while (cov) {
        const int o = __ffs(cov) - 1; cov &= cov - 1;
        const int k = sk[o];
        const float va = __shfl_sync(0xFFFFFFFFu, a,  k & 31);
        const float vb = __shfl_sync(0xFFFFFFFFu, bv, k & 31);
        const float vc = __shfl_sync(0xFFFFFFFFu, c,  k & 31);
        const float pk = (k < 32) ? va : ((k < 64) ? vb : vc);
        if (lane == 0) sobj_part[wid * MAXOBJ + o] += pk;
    }
}

// ---------------------------------------------------------------------------
// One CTA (8 warps) per batch element.
//  Phase 0 : labels -> per-object bounds/class; per-cell coverage bitmask.
//  Phase 1 : coalesced stream, 3-cell unroll (9 front-batched LDG); inline
//            class/conf sumsq AND per-object p_k accumulation (smem).
//  Phase 2 : per-object losses, smem-only.
//  Phase 3 : last-finished CTA -> deterministic batch reduction.
// ---------------------------------------------------------------------------
__global__ __launch_bounds__(256, 6)
void yolo_fused_kernel(const float* __restrict__ predicts,
                       const float* __restrict__ labels,
                       const int*   __restrict__ objects_num,
                       float* __restrict__ out, int B, int M)
{
    __shared__ float    spart[CELLS2 * 17];   // 16 class-sumsq partials / cell
    __shared__ float    scell[CELLS2 * 16];   // features 80..94 / cell
    __shared__ float    ssum2[CELLS2];        // class sumsq / cell
    __shared__ unsigned scover[CELLS2];       // object coverage bitmask / cell
    __shared__ float    slab[MAXOBJ * 5];
    __shared__ int      six0[MAXOBJ], six1[MAXOBJ], siy0[MAXOBJ], siy1[MAXOBJ], sk[MAXOBJ];
    __shared__ float    sobj_part[8 * MAXOBJ];  // per-warp per-object p_k partials
    __shared__ float    sred[8];
    __shared__ float    sS;
    __shared__ int      s_last;

    const int b    = blockIdx.x;
    const int tid  = threadIdx.x;
    const int lane = tid & 31;
    const int wid  = tid >> 5;

    const float* pb = predicts + (size_t)b * PRED_PER_B;

    int nobj = objects_num[b];
    if (nobj > M) nobj = M;
    if (nobj > MAXOBJ) nobj = MAXOBJ;

    // ---- Phase 0 ----
    sobj_part[tid] = 0.0f;
    for (int i = tid; i < nobj * 5; i += 256)
        slab[i] = labels[(size_t)b * M * 5 + i];
    __syncthreads();

    if (tid < nobj) {
        const float x = slab[tid * 5 + 0], y = slab[tid * 5 + 1];
        const float w = slab[tid * 5 + 2], h = slab[tid * 5 + 3];
        six0[tid] = (int)floorf((x - 0.5f * w) * (1.0f / CSF));
        six1[tid] = (int)fminf(ceilf((x + 0.5f * w) * (1.0f / CSF)), (float)CELLN);
        siy0[tid] = (int)floorf((y - 0.5f * h) * (1.0f / CSF));
        siy1[tid] = (int)fminf(ceilf((y + 0.5f * h) * (1.0f / CSF)), (float)CELLN);
        sk[tid]   = (int)slab[tid * 5 + 4];
    }
    __syncthreads();

    if (tid < CELLS2) {
        const int iy = tid / CELLN, ix = tid % CELLN;
        unsigned cov = 0;
        for (int o = 0; o < nobj; o++)
            if (ix >= six0[o] && ix < six1[o] && iy >= siy0[o] && iy < siy1[o])
                cov |= 1u << o;
        scover[tid] = cov;
    }
    __syncthreads();

    // ---- Phase 1: 3-cell unrolled stream ----
    float conf2 = 0.0f;
    for (int c0 = wid; c0 + 16 < CELLS2; c0 += 24) {
        const float* p0 = pb + c0 * FEAT;
        const float* p1 = pb + (c0 + 8) * FEAT;
        const float* p2 = pb + (c0 + 16) * FEAT;
        // front-batched loads (9 independent LDG)
        const float a0 = p0[lane], b0 = p0[lane + 32], q0 = (lane < 31) ? p0[lane + 64] : 0.0f;
        const float a1 = p1[lane], b1 = p1[lane + 32], q1 = (lane < 31) ? p1[lane + 64] : 0.0f;
        const float a2 = p2[lane], b2 = p2[lane + 32], q2 = (lane < 31) ? p2[lane + 64] : 0.0f;

        process_cell(c0,      a0, b0, q0, lane, wid, conf2, spart, scell, scover, sk, sobj_part);
        process_cell(c0 + 8,  a1, b1, q1, lane, wid, conf2, spart, scell, scover, sk, sobj_part);
        process_cell(c0 + 16, a2, b2, q2, lane, wid, conf2, spart, scell, scover, sk, sobj_part);
    }
    if (wid < 4) {   // tail cells 192..195
        const int cell = 192 + wid;
        const float* p = pb + cell * FEAT;
        const float a = p[lane], bv = p[lane + 32], q = (lane < 31) ? p[lane + 64] : 0.0f;
        process_cell(cell, a, bv, q, lane, wid, conf2, spart, scell, scover, sk, sobj_part);
    }
    #pragma unroll
    for (int off = 16; off; off >>= 1)
        conf2 += __shfl_xor_sync(0xFFFFFFFFu, conf2, off);
    if (lane == 0) sred[wid] = conf2;
    __syncthreads();

    // ---- Phase 1b: finish per-cell class sumsq ----
    if (tid < CELLS2) {
        const float* sp = spart + tid * 17;
        float s = 0.0f;
        #pragma unroll
        for (int i = 0; i < 16; i++) s += sp[i];
        ssum2[tid] = s;
    }
    if (tid == 0) {
        float s = 0.0f;
        #pragma unroll
        for (int i = 0; i < 8; i++) s += sred[i];
        sS = s;
    }
    __syncthreads();
    const float S_conf2 = sS;
    __syncthreads();            // sred reused below

    // ---- Phase 2: per-object losses (smem only) ----
    float wacc = 0.0f;
    for (int o = wid; o < nobj; o += 8) {
        const float x = slab[o * 5 + 0], y = slab[o * 5 + 1];
        const float w = slab[o * 5 + 2], h = slab[o * 5 + 3];
        const int ix0 = six0[o], iy0 = siy0[o];
        const int nx = max(0, six1[o] - ix0);
        const int ny = max(0, siy1[o] - iy0);
        const int cnt = nx * ny;

        // sum over masked cells of (ssum2 + 1)
        float cls = 0.0f;
        for (int t = lane; t < cnt; t += 32) {
            const int iy = iy0 + t / nx;
            const int ix = ix0 + t % nx;
            cls += ssum2[iy * CELLN + ix] + 1.0f;
        }
        #pragma unroll
        for (int off = 16; off; off >>= 1)
            cls += __shfl_xor_sync(0xFFFFFFFFu, cls, off);

        // p_k sum over the 8 warp partials (lanes 0..7)
        float pk = (lane < 8) ? sobj_part[lane * MAXOBJ + o] : 0.0f;
        pk += __shfl_xor_sync(0xFFFFFFFFu, pk, 4);
        pk += __shfl_xor_sync(0xFFFFFFFFu, pk, 2);
        pk += __shfl_xor_sync(0xFFFFFFFFu, pk, 1);

        const int cx = (int)floorf(x * (1.0f / CSF));
        const int cy = (int)floorf(y * (1.0f / CSF));
        const float* sc = scell + (cy * CELLN + cx) * 16;

        float ciou = -1e30f;
        float pC = 0.f, px = 0.f, py = 0.f, pw = 0.f, ph = 0.f;
        if (lane < BPC) {
            pC = sc[lane];                          // features 80..82
            const float* bx = sc + BPC + 4 * lane;  // features 83..94
            px = bx[0] * CSF + (float)cx * CSF;
            py = bx[1] * CSF + (float)cy * CSF;
            pw = bx[2] * IMGF;
            ph = bx[3] * IMGF;

            // CIoU exactly per reference (incl. centers-vs-widths enclose quirk)
            const float x11 = px - 0.5f * pw, x12 = px + 0.5f * pw;
            const float y11 = py - 0.5f * ph, y12 = py + 0.5f * ph;
            const float x21 = x - 0.5f * w,   x22 = x + 0.5f * w;
            const float y21 = y - 0.5f * h,   y22 = y + 0.5f * h;
            const float iw = fmaxf(fminf(x12, x22) - fmaxf(x11, x21), 0.0f);
            const float ih = fmaxf(fminf(y12, y22) - fmaxf(y11, y21), 0.0f);
            const float inter = iw * ih;
            const float uni = pw * ph + w * h - inter;
            const float iou = inter / (uni + EPSF);
            const float cd  = (px - x) * (px - x) + (py - y) * (py - y);
            const float el = fminf(px, x), er = fmaxf(pw, w);
            const float et = fminf(py, y), eb = fmaxf(ph, h);
            const float ed = (er - el) * (er - el) + (eb - et) * (eb - et);
            const float da = atanf(w / (h + EPSF)) - atanf(pw / (ph + EPSF));
            const float v  = INV_PI2_4 * da * da;
            const float alpha = v / (1.0f - iou + v + EPSF);
            ciou = iou - cd / (ed + EPSF) - alpha * v;
        }
        float m = ciou;
        m = fmaxf(m, __shfl_xor_sync(0xFFFFFFFFu, m, 1));
        m = fmaxf(m, __shfl_xor_sync(0xFFFFFFFFu, m, 2));

        float contrib = 0.0f;
        if (lane < BPC && ciou >= m) {
            const float d = pC - ciou;
            contrib += 0.5f * d * d;           // object loss
            contrib -= 0.25f * pC * pC;        // removed from noobject term
            const float dx = (px - x) * (1.0f / CSF);
            const float dy = (py - y) * (1.0f / CSF);
            const float swp = sqrtf(fminf(fmaxf(pw, 0.0f), IMGF));
            const float shp = sqrtf(fminf(fmaxf(ph, 0.0f), IMGF));
            const float dw = swp - sqrtf(fabsf(w));
            const float dh = shp - sqrtf(fabsf(h));
            contrib += 5.0f * (0.5f * dx * dx + 0.5f * dy * dy
                               + (0.5f * dw * dw) * (1.0f / IMGF)
                               + (0.5f * dh * dh) * (1.0f / IMGF));
        }
        contrib += __shfl_xor_sync(0xFFFFFFFFu, contrib, 1);
        contrib += __shfl_xor_sync(0xFFFFFFFFu, contrib, 2);

        if (lane == 0)
            wacc += 0.5f * cls - pk + contrib + 0.25f * S_conf2;
    }

    if (lane == 0) sred[wid] = wacc;
    __syncthreads();
    if (tid == 0) {
        float s = 0.0f;
        #pragma unroll
        for (int i = 0; i < 8; i++) s += sred[i];
        g_batch_loss[b] = s;
        __threadfence();
        int prev = atomicAdd(&g_count, 1);
        s_last = (prev == B - 1);
    }
    __syncthreads();

    // ---- Phase 3: last finished CTA -> deterministic final reduction ----
    if (s_last) {
        float a = 0.0f;
        for (int i = tid; i < B; i += 256) a += g_batch_loss[i];
        #pragma unroll
        for (int off = 16; off; off >>= 1)
            a += __shfl_xor_sync(0xFFFFFFFFu, a, off);
        if (lane == 0) sred[wid] = a;
        __syncthreads();
        if (tid == 0) {
            float s = 0.0f;
            #pragma unroll
            for (int i = 0; i < 8; i++) s += sred[i];
            out[0] = s / (float)B;
            g_count = 0;           // reset for next graph replay
        }
    }
}

extern "C" void kernel_launch(void* const* d_in, const int* in_sizes, int n_in,
                              void* d_out, int out_size)
{
    const float* predicts = (const float*)d_in[0];
    const float* labels   = (const float*)d_in[1];
    const int*   objnum   = (const int*)d_in[2];
    float* out = (float*)d_out;

    const int B = in_sizes[2];
    const int M = in_sizes[1] / (B * 5);

    yolo_fused_kernel<<<B, 256>>>(predicts, labels, objnum, out, B, M);
}

// round 6
// speedup vs baseline: 1.0369x; 1.0369x over previous
#include <cuda_runtime.h>
#include <cuda_bf16.h>
#include <math.h>

#define CELLN 14
#define NCLS  80
#define BPC   3
#define FEAT  95            // 80 + 3 + 12
#define CELLS2 196          // 14*14
#define PRED_PER_B 18620    // 196*95
#define CSF   32.0f
#define IMGF  448.0f
#define EPSF  1e-9f
#define INV_PI2_4 0.40528473456935109f   // 4/pi^2
#define MAXB  4096

__device__ float2 g_stats[MAXB * CELLS2];   // per (batch,cell): {class sumsq, conf sumsq}
__device__ float  g_obj_loss[MAXB * 64];    // per (batch,object) loss
__device__ int    g_count = 0;

// ---------------------------------------------------------------------------
// Kernel A: warp per 2 cells, grid-stride style coverage. Pure stream:
// 6 front-batched LDG, two interleaved butterfly reduce trees.
// ---------------------------------------------------------------------------
__global__ __launch_bounds__(256)
void yolo_stats_kernel(const float* __restrict__ P, int ncells)
{
    const int wg   = (blockIdx.x * 256 + threadIdx.x) >> 5;
    const int lane = threadIdx.x & 31;
    const int c0 = wg * 2;
    if (c0 >= ncells) return;
    const bool has1 = (c0 + 1) < ncells;

    const float* p0 = P + (size_t)c0 * FEAT;
    const float* p1 = p0 + FEAT;
    const float a0 = p0[lane], b0 = p0[lane + 32], q0 = (lane < 31) ? p0[lane + 64] : 0.0f;
    float a1 = 0.f, b1 = 0.f, q1 = 0.f;
    if (has1) { a1 = p1[lane]; b1 = p1[lane + 32]; q1 = (lane < 31) ? p1[lane + 64] : 0.0f; }

    float cls0 = a0 * a0 + b0 * b0;
    float cls1 = a1 * a1 + b1 * b1;
    float conf0 = 0.f, conf1 = 0.f;
    const float q02 = q0 * q0, q12 = q1 * q1;
    if (lane < 16)      { cls0 += q02;  cls1 += q12; }   // feat 64..79: class
    else if (lane < 19) { conf0 = q02;  conf1 = q12; }   // feat 80..82: confidence

    #pragma unroll
    for (int off = 16; off; off >>= 1) {
        cls0  += __shfl_xor_sync(0xFFFFFFFFu, cls0,  off);
        cls1  += __shfl_xor_sync(0xFFFFFFFFu, cls1,  off);
        conf0 += __shfl_xor_sync(0xFFFFFFFFu, conf0, off);
        conf1 += __shfl_xor_sync(0xFFFFFFFFu, conf1, off);
    }
    if (lane == 0) {
        g_stats[c0] = make_float2(cls0, conf0);
        if (has1) g_stats[c0 + 1] = make_float2(cls1, conf1);
    }
}

// ---------------------------------------------------------------------------
// Kernel B: one WARP per (batch, object). All gathers are one L2 round-trip
// deep and lane-parallel; ~7K concurrent warps hide the latency.
// Per-pair loss -> g_obj_loss (no atomics, deterministic); last finished
// block does the fixed-order final reduction.
// ---------------------------------------------------------------------------
__global__ __launch_bounds__(256)
void yolo_obj_kernel(const float* __restrict__ predicts,
                     const float* __restrict__ labels,
                     const int*   __restrict__ objects_num,
                     float* __restrict__ out, int B, int M, int nblocks)
{
    __shared__ float sred[8];
    __shared__ int   s_last;

    const int tid  = threadIdx.x;
    const int lane = tid & 31;
    const int wid  = tid >> 5;
    const int g    = blockIdx.x * 8 + wid;     // (batch,object) pair id
    const int nwork = B * M;

    if (g < nwork) {
        const int b = g / M;
        const int o = g - b * M;
        float loss = 0.0f;

        if (o < objects_num[b]) {
            const float* lb = labels + (size_t)b * M * 5 + o * 5;
            const float x = lb[0], y = lb[1], w = lb[2], h = lb[3];
            const int   k = (int)lb[4];

            const int ix0 = (int)floorf((x - 0.5f * w) * (1.0f / CSF));
            const int ix1 = (int)fminf(ceilf((x + 0.5f * w) * (1.0f / CSF)), (float)CELLN);
            const int iy0 = (int)floorf((y - 0.5f * h) * (1.0f / CSF));
            const int iy1 = (int)fminf(ceilf((y + 0.5f * h) * (1.0f / CSF)), (float)CELLN);
            const int nx  = max(0, ix1 - ix0);
            const int ny  = max(0, iy1 - iy0);
            const int cnt = nx * ny;

            const float*  pb = predicts + (size_t)b * PRED_PER_B;
            const float2* st = g_stats + b * CELLS2;

            // class loss over masked cells: stats.x - 2 p_k + 1  (lane-parallel)
            float cls = 0.0f;
            for (int t = lane; t < cnt; t += 32) {
                const int iy = iy0 + t / nx;
                const int ix = ix0 + t % nx;
                const int cell = iy * CELLN + ix;
                cls += __ldg(&st[cell].x) - 2.0f * __ldg(pb + cell * FEAT + k) + 1.0f;
            }
            // batch conf sum-of-squares (lane-parallel over 196 cells)
            float cs = 0.0f;
            #pragma unroll
            for (int i = 0; i < 7; i++) {
                const int c = lane + i * 32;
                if (c < CELLS2) cs += __ldg(&st[c].y);
            }
            #pragma unroll
            for (int off = 16; off; off >>= 1) {
                cls += __shfl_xor_sync(0xFFFFFFFFu, cls, off);
                cs  += __shfl_xor_sync(0xFFFFFFFFu, cs,  off);
            }

            // center cell
            const int cx = (int)floorf(x * (1.0f / CSF));
            const int cy = (int)floorf(y * (1.0f / CSF));
            const float* pc = pb + (cy * CELLN + cx) * FEAT;

            float ciou = -1e30f;
            float pC = 0.f, px = 0.f, py = 0.f, pw = 0.f, ph = 0.f;
            if (lane < BPC) {
                pC = __ldg(pc + NCLS + lane);
                const float* bx = pc + NCLS + BPC + 4 * lane;
                px = __ldg(bx + 0) * CSF + (float)cx * CSF;
                py = __ldg(bx + 1) * CSF + (float)cy * CSF;
                pw = __ldg(bx + 2) * IMGF;
                ph = __ldg(bx + 3) * IMGF;

                // CIoU exactly per reference (incl. centers-vs-widths enclose quirk)
                const float x11 = px - 0.5f * pw, x12 = px + 0.5f * pw;
                const float y11 = py - 0.5f * ph, y12 = py + 0.5f * ph;
                const float x21 = x - 0.5f * w,   x22 = x + 0.5f * w;
                const float y21 = y - 0.5f * h,   y22 = y + 0.5f * h;
                const float iw = fmaxf(fminf(x12, x22) - fmaxf(x11, x21), 0.0f);
                const float ih = fmaxf(fminf(y12, y22) - fmaxf(y11, y21), 0.0f);
                const float inter = iw * ih;
                const float uni = pw * ph + w * h - inter;
                const float iou = inter / (uni + EPSF);
                const float cd  = (px - x) * (px - x) + (py - y) * (py - y);
                const float el = fminf(px, x), er = fmaxf(pw, w);
                const float et = fminf(py, y), eb = fmaxf(ph, h);
                const float ed = (er - el) * (er - el) + (eb - et) * (eb - et);
                const float da = atanf(w / (h + EPSF)) - atanf(pw / (ph + EPSF));
                const float v  = INV_PI2_4 * da * da;
                const float alpha = v / (1.0f - iou + v + EPSF);
                ciou = iou - cd / (ed + EPSF) - alpha * v;
            }
            float m = ciou;
            m = fmaxf(m, __shfl_xor_sync(0xFFFFFFFFu, m, 1));
            m = fmaxf(m, __shfl_xor_sync(0xFFFFFFFFu, m, 2));

            float contrib = 0.0f;
            if (lane < BPC && ciou >= m) {
                const float d = pC - ciou;
                contrib += 0.5f * d * d;           // object loss
                contrib -= 0.25f * pC * pC;        // removed from noobject term
                const float dx = (px - x) * (1.0f / CSF);
                const float dy = (py - y) * (1.0f / CSF);
                const float swp = sqrtf(fminf(fmaxf(pw, 0.0f), IMGF));
                const float shp = sqrtf(fminf(fmaxf(ph, 0.0f), IMGF));
                const float dw = swp - sqrtf(fabsf(w));
                const float dh = shp - sqrtf(fabsf(h));
                contrib += 5.0f * (0.5f * dx * dx + 0.5f * dy * dy
                                   + (0.5f * dw * dw) * (1.0f / IMGF)
                                   + (0.5f * dh * dh) * (1.0f / IMGF));
            }
            contrib += __shfl_xor_sync(0xFFFFFFFFu, contrib, 1);
            contrib += __shfl_xor_sync(0xFFFFFFFFu, contrib, 2);

            loss = 0.5f * cls + contrib + 0.25f * cs;
        }
        if (lane == 0) g_obj_loss[g] = loss;
    }

    // ---- last-finished block: deterministic final reduction ----
    __syncthreads();
    if (tid == 0) {
        __threadfence();
        int prev = atomicAdd(&g_count, 1);
        s_last = (prev == nblocks - 1);
    }
    __syncthreads();
    if (s_last) {
        const int nwork2 = B * M;
        float a = 0.0f;
        for (int i = tid; i < nwork2; i += 256) a += g_obj_loss[i];
        #pragma unroll
        for (int off = 16; off; off >>= 1)
            a += __shfl_xor_sync(0xFFFFFFFFu, a, off);
        if (lane == 0) sred[wid] = a;
        __syncthreads();
        if (tid == 0) {
            float s = 0.0f;
            #pragma unroll
            for (int i = 0; i < 8; i++) s += sred[i];
            out[0] = s / (float)B;
            g_count = 0;           // reset for next graph replay
        }
    }
}

extern "C" void kernel_launch(void* const* d_in, const int* in_sizes, int n_in,
                              void* d_out, int out_size)
{
    const float* predicts = (const float*)d_in[0];
    const float* labels   = (const float*)d_in[1];
    const int*   objnum   = (const int*)d_in[2];
    float* out = (float*)d_out;

    const int B = in_sizes[2];
    const int M = in_sizes[1] / (B * 5);
    const int ncells = B * CELLS2;

    const int gridA = ((ncells + 1) / 2 + 7) / 8;       // warp per 2 cells
    const int gridB = (B * M + 7) / 8;                  // warp per (b,o)

    yolo_stats_kernel<<<gridA, 256>>>(predicts, ncells);
    yolo_obj_kernel<<<gridB, 256>>>(predicts, labels, objnum, out, B, M, gridB);
}